// round 13
// baseline (speedup 1.0000x reference)
#include <cuda_runtime.h>
#include <cstdint>

// CondConv2d via fp16 mma.sync.m16n8k16 implicit GEMM (f32 accumulate).
// R13: R11 tiling, but staging is direct LDG->cvt->STS into double-buffered
// xsh: no f32 scratch, no convert phase, ONE barrier per job.
// CTA = 8h x 64w x 32co, 2 h-tiles (4 jobs of 16 ci); 256 threads / 8 warps;
// warp = 2h x 32px x 32co.

#define B_    16
#define CIN_  32
#define HW_   256
#define COUT_ 32
#define NEXP  8
#define NPARAM 9216

// ---- smem layout in 4-byte units ----
#define XPH    76                 // 760 % 32 == 24 -> B-frag banks distinct
#define XSH_SZ 6080               // 8 jpairs x 10 rows x 76
#define XSH0_U 0
#define XSH1_U 6080
#define WS_U   12160              // 2 halves x 2304 words (k16 fragment order)
#define BIAS_U 16768
#define SMEM_U 16800
#define SMEM_BYTES (SMEM_U * 4)   // 67200 B -> 2 CTA/SM (regs bound anyway)

__device__ uint32_t g_wt_h[B_ * 4608];   // [b][cc][t][mt][lane][w] f16x2 words
__device__ float    g_bias[B_ * COUT_];

__device__ __forceinline__ uint32_t smem_u32(const void* p) {
    uint32_t a;
    asm("{ .reg .u64 t; cvta.to.shared.u64 t, %1; cvt.u32.u64 %0, t; }" : "=r"(a) : "l"(p));
    return a;
}
__device__ __forceinline__ uint32_t pack_f16x2(float hi, float lo) {
    uint32_t d;
    asm("cvt.rn.f16x2.f32 %0, %1, %2;" : "=r"(d) : "f"(hi), "f"(lo));
    return d;
}
__device__ __forceinline__ void mma_f16(float c[4], const uint32_t a[4],
                                        uint32_t b0, uint32_t b1) {
    asm volatile(
        "mma.sync.aligned.m16n8k16.row.col.f32.f16.f16.f32 "
        "{%0,%1,%2,%3}, {%4,%5,%6,%7}, {%8,%9}, {%0,%1,%2,%3};"
        : "+f"(c[0]), "+f"(c[1]), "+f"(c[2]), "+f"(c[3])
        : "r"(a[0]), "r"(a[1]), "r"(a[2]), "r"(a[3]), "r"(b0), "r"(b1));
}
__device__ __forceinline__ void cp_async16(uint32_t dst, const void* src) {
    asm volatile("cp.async.cg.shared.global [%0], [%1], 16;"
                 :: "r"(dst), "l"(src) : "memory");
}
#define CP_COMMIT() asm volatile("cp.async.commit_group;" ::: "memory")
#define CP_WAIT0()  asm volatile("cp.async.wait_group 0;" ::: "memory")

// ---------------------------------------------------------------------------
// Kernel 1: mix experts -> fragment-ordered fp16 weights + bias (unchanged).
// word index (per b): ((cc*9 + t)*2 + mt)*128 + lane*4 + w
//   co = mt*16 + g + (w&1)*8 ; ci = cc*16 + 2*tig + (w>>1)*8, pack {ci, ci+1}.
// ---------------------------------------------------------------------------
__global__ void condconv_prep_kernel(const float* __restrict__ rw,
                                     const float* __restrict__ ew,
                                     const float* __restrict__ eb) {
    int b = blockIdx.x, cc = blockIdx.y;
    int tid = threadIdx.x;
    float r[NEXP];
#pragma unroll
    for (int e = 0; e < NEXP; e++) r[e] = rw[b * NEXP + e];

    for (int i = tid; i < 2304; i += 256) {
        int t    = i >> 8;
        int r2   = i & 255;
        int mt   = r2 >> 7;
        int lane = (r2 >> 2) & 31;
        int w    = r2 & 3;
        int g = lane >> 2, tig = lane & 3;
        int co = mt * 16 + g + (w & 1) * 8;
        int ci = cc * 16 + 2 * tig + (w >> 1) * 8;
        int src = co * (CIN_ * 9) + ci * 9 + t;
        float s_lo = 0.f, s_hi = 0.f;
#pragma unroll
        for (int e = 0; e < NEXP; e++) {
            s_lo += r[e] * ew[e * NPARAM + src];
            s_hi += r[e] * ew[e * NPARAM + src + 9];   // ci+1
        }
        g_wt_h[(b * 2 + cc) * 2304 + i] = pack_f16x2(s_hi, s_lo);
    }
    if (cc == 0 && tid < COUT_) {
        float s = 0.f;
#pragma unroll
        for (int e = 0; e < NEXP; e++) s += r[e] * eb[e * COUT_ + tid];
        g_bias[b * COUT_ + tid] = s;
    }
}

// ---------------------------------------------------------------------------
// direct staging of one 16-ci job: LDG.128 (2 planes) -> f16x2 -> STS.128.
// xq = first plane of the ci-half. xsh col c <-> iw = w0 - 4 + c.
// ---------------------------------------------------------------------------
__device__ __forceinline__ void stage_direct(uint32_t* __restrict__ xsh,
                                             const float* __restrict__ xq,
                                             int h0, int w0, int tid) {
    // interior: 8 jpairs x 10 rows x 16 vec4 (cols w0..w0+63 -> smem 4..67)
    for (int i = tid; i < 1280; i += 256) {
        int v    = i & 15;
        int rest = i >> 4;
        int j    = rest / 10;
        int row  = rest - j * 10;
        int ih   = h0 - 1 + row;
        float4 f0, f1;
        if ((unsigned)ih < 256u) {
            const float* p0 = xq + (size_t)(2 * j) * (HW_ * HW_) + ih * HW_ + w0 + 4 * v;
            f0 = *(const float4*)p0;
            f1 = *(const float4*)(p0 + HW_ * HW_);
        } else {
            f0 = make_float4(0.f, 0.f, 0.f, 0.f);
            f1 = f0;
        }
        uint4 o;
        o.x = pack_f16x2(f1.x, f0.x);
        o.y = pack_f16x2(f1.y, f0.y);
        o.z = pack_f16x2(f1.z, f0.z);
        o.w = pack_f16x2(f1.w, f0.w);
        *(uint4*)(xsh + j * (10 * XPH) + row * XPH + 4 + 4 * v) = o;
    }
    // halo: 8 jpairs x 10 rows x 2 sides (w0-1 -> col 3, w0+64 -> col 68)
    for (int i = tid; i < 160; i += 256) {
        int side = i & 1;
        int rest = i >> 1;
        int j    = rest / 10;
        int row  = rest - j * 10;
        int ih = h0 - 1 + row;
        int iw = side ? (w0 + 64) : (w0 - 1);
        float f0 = 0.f, f1 = 0.f;
        if (((unsigned)ih < 256u) && ((unsigned)iw < 256u)) {
            const float* p0 = xq + (size_t)(2 * j) * (HW_ * HW_) + ih * HW_ + iw;
            f0 = p0[0];
            f1 = p0[HW_ * HW_];
        }
        xsh[j * (10 * XPH) + row * XPH + (side ? 68 : 3)] = pack_f16x2(f1, f0);
    }
}

// ---------------------------------------------------------------------------
// compute one 16-ci half (R11's validated kernel: 2h x 32px x 32co per warp)
// ---------------------------------------------------------------------------
__device__ __forceinline__ void compute_half(const uint32_t* xsh, const uint32_t* ws,
                                             float acc[2][2][4][4],
                                             int lane, int g, int tig, int wy, int wh) {
    const uint4* wf = (const uint4*)ws + lane;
    const uint32_t* xf = xsh + (2 * wy) * XPH + wh * 32 + g + 3 + tig * (10 * XPH);

#pragma unroll
    for (int kw = 0; kw < 3; kw++) {
        uint32_t B0[4][4], B1[4][4];
#pragma unroll
        for (int xr = 0; xr < 4; xr++) {
            const uint32_t* xt = xf + xr * XPH + kw;
#pragma unroll
            for (int nt = 0; nt < 4; nt++) {
                B0[xr][nt] = xt[nt * 8];
                B1[xr][nt] = xt[nt * 8 + 4 * (10 * XPH)];
            }
        }
#pragma unroll
        for (int kh = 0; kh < 3; kh++) {
            const int t = kh * 3 + kw;
            uint4 q0 = wf[(t * 2) * 32];
            uint4 q1 = wf[(t * 2 + 1) * 32];
            uint32_t a0[4] = {q0.x, q0.y, q0.z, q0.w};
            uint32_t a1[4] = {q1.x, q1.y, q1.z, q1.w};
#pragma unroll
            for (int r = 0; r < 2; r++) {
                const int xr = r + kh;
#pragma unroll
                for (int nt = 0; nt < 4; nt++) {
                    mma_f16(acc[r][0][nt], a0, B0[xr][nt], B1[xr][nt]);
                    mma_f16(acc[r][1][nt], a1, B0[xr][nt], B1[xr][nt]);
                }
            }
        }
    }
}

__device__ __forceinline__ void store_tile(float acc[2][2][4][4], float* __restrict__ out,
                                           const float* bs, int b, int oh0, int w0,
                                           int g, int tig, int wy, int wh) {
#pragma unroll
    for (int r = 0; r < 2; r++) {
        const int oh = oh0 + 2 * wy + r;
#pragma unroll
        for (int mt = 0; mt < 2; mt++) {
#pragma unroll
            for (int nt = 0; nt < 4; nt++) {
                int co = mt * 16 + g;
                int pw = w0 + wh * 32 + nt * 8 + 2 * tig;
                float2 v0, v1;
                v0.x = acc[r][mt][nt][0] + bs[co];
                v0.y = acc[r][mt][nt][1] + bs[co];
                v1.x = acc[r][mt][nt][2] + bs[co + 8];
                v1.y = acc[r][mt][nt][3] + bs[co + 8];
                *(float2*)&out[(((size_t)b * COUT_ + co)     * HW_ + oh) * HW_ + pw] = v0;
                *(float2*)&out[(((size_t)b * COUT_ + co + 8) * HW_ + oh) * HW_ + pw] = v1;
            }
        }
    }
}

// ---------------------------------------------------------------------------
// Kernel 2: conv. Grid (4, 16, 16); 256 threads, 8 warps; 2 h-tiles per CTA.
// jobs j=0..3: tile = j>>1 (h0 = hb + 8*tile), half = j&1.
// Loop: compute(j) -> stage(j+1) -> bar  (one barrier per job).
// ---------------------------------------------------------------------------
__global__ __launch_bounds__(256, 2)
void condconv_mma_kernel(const float* __restrict__ x, float* __restrict__ out) {
    extern __shared__ float sm[];
    const uint32_t sbase = smem_u32(sm);

    const int b  = blockIdx.z;
    const int hb = blockIdx.y * 16;      // 2-tile strip base row
    const int w0 = blockIdx.x * 64;
    const int tid = threadIdx.x;
    const int lane = tid & 31, wid = tid >> 5;
    const int g = lane >> 2, tig = lane & 3;
    const int wy = wid >> 1, wh = wid & 1;

    const uint32_t* gw = g_wt_h + b * 4608;
    const float* xb = x + (size_t)b * CIN_ * HW_ * HW_;
    uint32_t* xsh_p[2] = {(uint32_t*)(sm + XSH0_U), (uint32_t*)(sm + XSH1_U)};
    const uint32_t* ws = (const uint32_t*)(sm + WS_U);

    // prologue: weights via cp.async (overlaps the job-0 LDG staging)
    for (int i = tid; i < 1152; i += 256)
        cp_async16(sbase + (WS_U + i * 4) * 4, gw + i * 4);
    CP_COMMIT();

    if (tid < COUT_) sm[BIAS_U + tid] = g_bias[b * COUT_ + tid];

    stage_direct(xsh_p[0], xb, hb, w0, tid);   // job0 = tile0, half0

    float acc[2][2][4][4];
#pragma unroll
    for (int r = 0; r < 2; r++)
#pragma unroll
        for (int mt = 0; mt < 2; mt++)
#pragma unroll
            for (int nt = 0; nt < 4; nt++)
#pragma unroll
                for (int i = 0; i < 4; i++) acc[r][mt][nt][i] = 0.f;

    CP_WAIT0();
    __syncthreads();   // job0 + weights visible

#pragma unroll 1
    for (int j = 0; j < 4; j++) {
        compute_half(xsh_p[j & 1], ws + (j & 1) * 2304, acc, lane, g, tig, wy, wh);

        if (j == 1) {                    // tile 0 complete
            store_tile(acc, out, sm + BIAS_U, b, hb, w0, g, tig, wy, wh);
#pragma unroll
            for (int r = 0; r < 2; r++)
#pragma unroll
                for (int mt = 0; mt < 2; mt++)
#pragma unroll
                    for (int nt = 0; nt < 4; nt++)
#pragma unroll
                        for (int i = 0; i < 4; i++) acc[r][mt][nt][i] = 0.f;
        }

        if (j < 3) {
            int nj = j + 1;
            stage_direct(xsh_p[nj & 1],
                         xb + (size_t)((nj & 1) * 16) * (HW_ * HW_),
                         hb + (nj >> 1) * 8, w0, tid);
            __syncthreads();             // xsh[(j+1)&1] ready; xsh[j&1] free
        }
    }

    store_tile(acc, out, sm + BIAS_U, b, hb + 8, w0, g, tig, wy, wh);
}

// ---------------------------------------------------------------------------
extern "C" void kernel_launch(void* const* d_in, const int* in_sizes, int n_in,
                              void* d_out, int out_size) {
    const float* x  = (const float*)d_in[0];
    const float* rw = (const float*)d_in[1];
    const float* ew = (const float*)d_in[2];
    const float* eb = (const float*)d_in[3];
    float* out = (float*)d_out;

    condconv_prep_kernel<<<dim3(B_, 2), 256>>>(rw, ew, eb);

    cudaFuncSetAttribute(condconv_mma_kernel,
                         cudaFuncAttributeMaxDynamicSharedMemorySize, SMEM_BYTES);
    dim3 grid(HW_ / 64, HW_ / 16, B_);
    condconv_mma_kernel<<<grid, 256, SMEM_BYTES>>>(x, out);
}

// round 14
// speedup vs baseline: 1.1256x; 1.1256x over previous
#include <cuda_runtime.h>
#include <cstdint>

// CondConv2d via fp16 mma.sync.m16n8k16 implicit GEMM (f32 accumulate).
// R14: persistent CTAs (304 = 2/SM), each owns a contiguous block of 6-7
// tiles (8h x 64w), R11's cp.async->convert->compute pipeline run
// continuously across tiles; double-slotted per-batch weights.
// Warp = 2h x 32px x 32co; job = tile x 16-ci half.

#define B_    16
#define CIN_  32
#define HW_   256
#define COUT_ 32
#define NEXP  8
#define NPARAM 9216

#define NTILES  2048              // 16 b x 32 hy x 4 hx
#define NCTA    304

// ---- smem layout in 4-byte units ----
#define RAWP   72                 // raw f32 pitch
#define SCR_U  0                  // 16 planes x 10 rows x 72 = 11520 words
#define XPH    76                 // 760 % 32 == 24 -> B-frag banks distinct
#define XSH_U  11520              // 8 jpairs x 10 rows x 76 = 6080 words
#define WS_U   17600              // 2 slots x 4608 words (per-b fp16 weights)
#define SMEM_U 26816
#define SMEM_BYTES (SMEM_U * 4)   // 107264 B -> 2 CTA/SM

__device__ uint32_t g_wt_h[B_ * 4608];   // [b][cc][t][mt][lane][w] f16x2 words
__device__ float    g_bias[B_ * COUT_];

__device__ __forceinline__ uint32_t smem_u32(const void* p) {
    uint32_t a;
    asm("{ .reg .u64 t; cvta.to.shared.u64 t, %1; cvt.u32.u64 %0, t; }" : "=r"(a) : "l"(p));
    return a;
}
__device__ __forceinline__ uint32_t pack_f16x2(float hi, float lo) {
    uint32_t d;
    asm("cvt.rn.f16x2.f32 %0, %1, %2;" : "=r"(d) : "f"(hi), "f"(lo));
    return d;
}
__device__ __forceinline__ void mma_f16(float c[4], const uint32_t a[4],
                                        uint32_t b0, uint32_t b1) {
    asm volatile(
        "mma.sync.aligned.m16n8k16.row.col.f32.f16.f16.f32 "
        "{%0,%1,%2,%3}, {%4,%5,%6,%7}, {%8,%9}, {%0,%1,%2,%3};"
        : "+f"(c[0]), "+f"(c[1]), "+f"(c[2]), "+f"(c[3])
        : "r"(a[0]), "r"(a[1]), "r"(a[2]), "r"(a[3]), "r"(b0), "r"(b1));
}
__device__ __forceinline__ void cp_async4(uint32_t dst, const void* src, uint32_t sz) {
    asm volatile("cp.async.ca.shared.global [%0], [%1], 4, %2;"
                 :: "r"(dst), "l"(src), "r"(sz) : "memory");
}
__device__ __forceinline__ void cp_async16(uint32_t dst, const void* src) {
    asm volatile("cp.async.cg.shared.global [%0], [%1], 16;"
                 :: "r"(dst), "l"(src) : "memory");
}
__device__ __forceinline__ void cp_async16z(uint32_t dst, const void* src, uint32_t sz) {
    asm volatile("cp.async.cg.shared.global [%0], [%1], 16, %2;"
                 :: "r"(dst), "l"(src), "r"(sz) : "memory");
}
#define CP_COMMIT() asm volatile("cp.async.commit_group;" ::: "memory")
#define CP_WAIT0()  asm volatile("cp.async.wait_group 0;" ::: "memory")

// ---------------------------------------------------------------------------
// Kernel 1: mix experts -> fragment-ordered fp16 weights + bias (unchanged).
// ---------------------------------------------------------------------------
__global__ void condconv_prep_kernel(const float* __restrict__ rw,
                                     const float* __restrict__ ew,
                                     const float* __restrict__ eb) {
    int b = blockIdx.x, cc = blockIdx.y;
    int tid = threadIdx.x;
    float r[NEXP];
#pragma unroll
    for (int e = 0; e < NEXP; e++) r[e] = rw[b * NEXP + e];

    for (int i = tid; i < 2304; i += 256) {
        int t    = i >> 8;
        int r2   = i & 255;
        int mt   = r2 >> 7;
        int lane = (r2 >> 2) & 31;
        int w    = r2 & 3;
        int g = lane >> 2, tig = lane & 3;
        int co = mt * 16 + g + (w & 1) * 8;
        int ci = cc * 16 + 2 * tig + (w >> 1) * 8;
        int src = co * (CIN_ * 9) + ci * 9 + t;
        float s_lo = 0.f, s_hi = 0.f;
#pragma unroll
        for (int e = 0; e < NEXP; e++) {
            s_lo += r[e] * ew[e * NPARAM + src];
            s_hi += r[e] * ew[e * NPARAM + src + 9];
        }
        g_wt_h[(b * 2 + cc) * 2304 + i] = pack_f16x2(s_hi, s_lo);
    }
    if (cc == 0 && tid < COUT_) {
        float s = 0.f;
#pragma unroll
        for (int e = 0; e < NEXP; e++) s += r[e] * eb[e * COUT_ + tid];
        g_bias[b * COUT_ + tid] = s;
    }
}

// ---------------------------------------------------------------------------
// stage 16 planes of one job (R11 verbatim).
// ---------------------------------------------------------------------------
__device__ __forceinline__ void stage_raw(uint32_t scr, const float* __restrict__ xq,
                                          int h0, int w0, int tid) {
    for (int i = tid; i < 2560; i += 256) {
        int v    = i & 15;
        int rest = i >> 4;
        int pl   = rest / 10;
        int row  = rest - pl * 10;
        int ih   = h0 - 1 + row;
        bool ok = (unsigned)ih < 256u;
        const float* src = xq + (size_t)pl * (HW_ * HW_) + (ok ? ih * HW_ : 0) + w0 + 4 * v;
        cp_async16z(scr + (uint32_t)(pl * (10 * RAWP) + row * RAWP + 4 + 4 * v) * 4,
                    src, ok ? 16u : 0u);
    }
    for (int i = tid; i < 320; i += 256) {
        int side = i & 1;
        int rest = i >> 1;
        int pl   = rest / 10;
        int row  = rest - pl * 10;
        int ih = h0 - 1 + row;
        int iw = side ? (w0 + 64) : (w0 - 1);
        bool ok = ((unsigned)ih < 256u) && ((unsigned)iw < 256u);
        const float* src = xq + (size_t)pl * (HW_ * HW_) + (ok ? (ih * HW_ + iw) : 0);
        cp_async4(scr + (uint32_t)(pl * (10 * RAWP) + row * RAWP + (side ? 68 : 3)) * 4,
                  src, ok ? 4u : 0u);
    }
}

// convert scr f32 (16 planes) -> xsh packed f16x2 (R11 verbatim)
__device__ __forceinline__ void convert_half(const float* scr, uint32_t* xsh, int tid) {
    for (int i = tid; i < 2800; i += 256) {
        int j   = i / 350;
        int r1  = i - j * 350;
        int row = r1 / 35;
        int p2  = r1 - row * 35;
        const float* s0 = scr + (2 * j)     * (10 * RAWP) + row * RAWP + 2 * p2;
        const float* s1 = scr + (2 * j + 1) * (10 * RAWP) + row * RAWP + 2 * p2;
        float2 f0 = *(const float2*)s0;
        float2 f1 = *(const float2*)s1;
        uint2 o;
        o.x = pack_f16x2(f1.x, f0.x);
        o.y = pack_f16x2(f1.y, f0.y);
        *(uint2*)(xsh + j * (10 * XPH) + row * XPH + 2 * p2) = o;
    }
}

// compute one 16-ci half (R11 verbatim)
__device__ __forceinline__ void compute_half(const uint32_t* xsh, const uint32_t* ws,
                                             float acc[2][2][4][4],
                                             int lane, int g, int tig, int wy, int wh) {
    const uint4* wf = (const uint4*)ws + lane;
    const uint32_t* xf = xsh + (2 * wy) * XPH + wh * 32 + g + 3 + tig * (10 * XPH);

#pragma unroll
    for (int kw = 0; kw < 3; kw++) {
        uint32_t B0[4][4], B1[4][4];
#pragma unroll
        for (int xr = 0; xr < 4; xr++) {
            const uint32_t* xt = xf + xr * XPH + kw;
#pragma unroll
            for (int nt = 0; nt < 4; nt++) {
                B0[xr][nt] = xt[nt * 8];
                B1[xr][nt] = xt[nt * 8 + 4 * (10 * XPH)];
            }
        }
#pragma unroll
        for (int kh = 0; kh < 3; kh++) {
            const int t = kh * 3 + kw;
            uint4 q0 = wf[(t * 2) * 32];
            uint4 q1 = wf[(t * 2 + 1) * 32];
            uint32_t a0[4] = {q0.x, q0.y, q0.z, q0.w};
            uint32_t a1[4] = {q1.x, q1.y, q1.z, q1.w};
#pragma unroll
            for (int r = 0; r < 2; r++) {
                const int xr = r + kh;
#pragma unroll
                for (int nt = 0; nt < 4; nt++) {
                    mma_f16(acc[r][0][nt], a0, B0[xr][nt], B1[xr][nt]);
                    mma_f16(acc[r][1][nt], a1, B0[xr][nt], B1[xr][nt]);
                }
            }
        }
    }
}

// store one tile; bias read straight from global (tiny, L1/L2 cached)
__device__ __forceinline__ void store_tile(float acc[2][2][4][4], float* __restrict__ out,
                                           int b, int oh0, int w0,
                                           int g, int tig, int wy, int wh) {
    const float* bb = g_bias + b * COUT_;
#pragma unroll
    for (int r = 0; r < 2; r++) {
        const int oh = oh0 + 2 * wy + r;
#pragma unroll
        for (int mt = 0; mt < 2; mt++) {
            int co = mt * 16 + g;
            float b0 = bb[co], b1 = bb[co + 8];
#pragma unroll
            for (int nt = 0; nt < 4; nt++) {
                int pw = w0 + wh * 32 + nt * 8 + 2 * tig;
                float2 v0, v1;
                v0.x = acc[r][mt][nt][0] + b0;
                v0.y = acc[r][mt][nt][1] + b0;
                v1.x = acc[r][mt][nt][2] + b1;
                v1.y = acc[r][mt][nt][3] + b1;
                *(float2*)&out[(((size_t)b * COUT_ + co)     * HW_ + oh) * HW_ + pw] = v0;
                *(float2*)&out[(((size_t)b * COUT_ + co + 8) * HW_ + oh) * HW_ + pw] = v1;
            }
        }
    }
}

// ---------------------------------------------------------------------------
// Kernel 2: persistent conv. Grid (304); 256 threads, 8 warps.
// Tile id = b*128 + hy*4 + hx (b-major, contiguous per CTA block).
// Job jj in [0, 2*ntiles): tile = first + (jj>>1), half = jj&1.
// Per-job: wait -> bar -> convert -> bar -> prefetch(jj+1) -> compute(jj).
// ---------------------------------------------------------------------------
__global__ __launch_bounds__(256, 2)
void condconv_mma_kernel(const float* __restrict__ x, float* __restrict__ out) {
    extern __shared__ float sm[];
    const uint32_t sbase = smem_u32(sm);

    const int c   = blockIdx.x;
    const int tid = threadIdx.x;
    const int lane = tid & 31, wid = tid >> 5;
    const int g = lane >> 2, tig = lane & 3;
    const int wy = wid >> 1, wh = wid & 1;

    const int t_first = (c * NTILES) / NCTA;
    const int t_end   = ((c + 1) * NTILES) / NCTA;
    const int njobs   = 2 * (t_end - t_first);
    if (njobs <= 0) return;

    uint32_t* xsh = (uint32_t*)(sm + XSH_U);
    const uint32_t scr_a = sbase + SCR_U * 4;

    // weight slots: b held in each
    int b_slot[2] = {-1, -1};

    // prologue: weights(b of first tile) -> slot 0, raw(job0), one group
    {
        int b0 = t_first >> 7;
        for (int i = tid; i < 1152; i += 256)
            cp_async16(sbase + (WS_U + i * 4) * 4, g_wt_h + b0 * 4608 + i * 4);
        b_slot[0] = b0;
        int rem = t_first & 127;
        stage_raw(scr_a, x + (size_t)b0 * CIN_ * HW_ * HW_,
                  (rem >> 2) * 8, (rem & 3) * 64, tid);
        CP_COMMIT();
    }

    float acc[2][2][4][4];
#pragma unroll
    for (int r = 0; r < 2; r++)
#pragma unroll
        for (int mt = 0; mt < 2; mt++)
#pragma unroll
            for (int nt = 0; nt < 4; nt++)
#pragma unroll
                for (int i = 0; i < 4; i++) acc[r][mt][nt][i] = 0.f;

#pragma unroll 1
    for (int jj = 0; jj < njobs; jj++) {
        const int tile = t_first + (jj >> 1);
        const int half = jj & 1;
        const int b    = tile >> 7;
        const int rem  = tile & 127;
        const int h0   = (rem >> 2) * 8;
        const int w0   = (rem & 3) * 64;

        CP_WAIT0();
        __syncthreads();               // raw(jj) (+ any weights) visible
        convert_half(sm + SCR_U, xsh, tid);
        __syncthreads();               // xsh ready; scr free

        // prefetch job jj+1 (raw + weights if new batch) under compute(jj)
        if (jj + 1 < njobs) {
            const int ntile = t_first + ((jj + 1) >> 1);
            const int nhalf = (jj + 1) & 1;
            const int nb    = ntile >> 7;
            const int nrem  = ntile & 127;
            if (nb != b_slot[0] && nb != b_slot[1]) {
                int victim = (b_slot[0] == b) ? 1 : 0;   // don't evict current b
                for (int i = tid; i < 1152; i += 256)
                    cp_async16(sbase + (WS_U + victim * 4608 * 4 + i * 16),
                               g_wt_h + nb * 4608 + i * 4);
                b_slot[victim] = nb;
            }
            stage_raw(scr_a,
                      x + ((size_t)nb * CIN_ + nhalf * 16) * (HW_ * HW_),
                      (nrem >> 2) * 8, (nrem & 3) * 64, tid);
            CP_COMMIT();
        }

        const int slot = (b_slot[0] == b) ? 0 : 1;
        const uint32_t* ws = (const uint32_t*)(sm + WS_U) + slot * 4608 + half * 2304;
        compute_half(xsh, ws, acc, lane, g, tig, wy, wh);

        if (half == 1) {               // tile complete
            store_tile(acc, out, b, h0, w0, g, tig, wy, wh);
#pragma unroll
            for (int r = 0; r < 2; r++)
#pragma unroll
                for (int mt = 0; mt < 2; mt++)
#pragma unroll
                    for (int nt = 0; nt < 4; nt++)
#pragma unroll
                        for (int i = 0; i < 4; i++) acc[r][mt][nt][i] = 0.f;
        }
    }
}

// ---------------------------------------------------------------------------
extern "C" void kernel_launch(void* const* d_in, const int* in_sizes, int n_in,
                              void* d_out, int out_size) {
    const float* x  = (const float*)d_in[0];
    const float* rw = (const float*)d_in[1];
    const float* ew = (const float*)d_in[2];
    const float* eb = (const float*)d_in[3];
    float* out = (float*)d_out;

    condconv_prep_kernel<<<dim3(B_, 2), 256>>>(rw, ew, eb);

    cudaFuncSetAttribute(condconv_mma_kernel,
                         cudaFuncAttributeMaxDynamicSharedMemorySize, SMEM_BYTES);
    condconv_mma_kernel<<<NCTA, 256, SMEM_BYTES>>>(x, out);
}

// round 15
// speedup vs baseline: 1.1514x; 1.0230x over previous
#include <cuda_runtime.h>
#include <cstdint>

// CondConv2d via fp16 mma.sync.m16n8k16 implicit GEMM (f32 accumulate).
// R15: R11 pipeline minus the convert phase — compute reads raw f32 scratch
// directly, packing B fragments on the fly (2x LDS.32 + cvt.rn.f16x2).
// One barrier per job. scr double-buffered, plane stride padded (724 words)
// for conflict-free paired-plane loads.
// CTA = 8h x 64w x 32co, 2 h-tiles (4 jobs of 16 ci); 256 threads / 8 warps;
// warp = 2h x 32px x 32co.

#define B_    16
#define CIN_  32
#define HW_   256
#define COUT_ 32
#define NEXP  8
#define NPARAM 9216

// ---- smem layout in 4-byte units ----
#define RAWP   72                 // row pitch (words); col c <-> iw = w0 - 4 + c
#define PS     724                // plane stride: 2*724 % 32 == 8 -> tig banks {0,8,16,24}
#define SCR_SZ 11584              // 16 planes x 724
#define SCR0_U 0
#define SCR1_U 11584
#define WS_U   23168              // 2 halves x 2304 words (k16 fragment order)
#define BIAS_U 27776
#define SMEM_U 27808
#define SMEM_BYTES (SMEM_U * 4)   // 111232 B -> 2 CTA/SM

__device__ uint32_t g_wt_h[B_ * 4608];   // [b][cc][t][mt][lane][w] f16x2 words
__device__ float    g_bias[B_ * COUT_];

__device__ __forceinline__ uint32_t smem_u32(const void* p) {
    uint32_t a;
    asm("{ .reg .u64 t; cvta.to.shared.u64 t, %1; cvt.u32.u64 %0, t; }" : "=r"(a) : "l"(p));
    return a;
}
__device__ __forceinline__ uint32_t pack_f16x2(float hi, float lo) {
    uint32_t d;
    asm("cvt.rn.f16x2.f32 %0, %1, %2;" : "=r"(d) : "f"(hi), "f"(lo));
    return d;
}
__device__ __forceinline__ void mma_f16(float c[4], const uint32_t a[4],
                                        uint32_t b0, uint32_t b1) {
    asm volatile(
        "mma.sync.aligned.m16n8k16.row.col.f32.f16.f16.f32 "
        "{%0,%1,%2,%3}, {%4,%5,%6,%7}, {%8,%9}, {%0,%1,%2,%3};"
        : "+f"(c[0]), "+f"(c[1]), "+f"(c[2]), "+f"(c[3])
        : "r"(a[0]), "r"(a[1]), "r"(a[2]), "r"(a[3]), "r"(b0), "r"(b1));
}
__device__ __forceinline__ void cp_async4(uint32_t dst, const void* src, uint32_t sz) {
    asm volatile("cp.async.ca.shared.global [%0], [%1], 4, %2;"
                 :: "r"(dst), "l"(src), "r"(sz) : "memory");
}
__device__ __forceinline__ void cp_async16(uint32_t dst, const void* src) {
    asm volatile("cp.async.cg.shared.global [%0], [%1], 16;"
                 :: "r"(dst), "l"(src) : "memory");
}
__device__ __forceinline__ void cp_async16z(uint32_t dst, const void* src, uint32_t sz) {
    asm volatile("cp.async.cg.shared.global [%0], [%1], 16, %2;"
                 :: "r"(dst), "l"(src), "r"(sz) : "memory");
}
#define CP_COMMIT() asm volatile("cp.async.commit_group;" ::: "memory")
#define CP_WAIT0()  asm volatile("cp.async.wait_group 0;" ::: "memory")

// ---------------------------------------------------------------------------
// Kernel 1: mix experts -> fragment-ordered fp16 weights + bias (unchanged).
// ---------------------------------------------------------------------------
__global__ void condconv_prep_kernel(const float* __restrict__ rw,
                                     const float* __restrict__ ew,
                                     const float* __restrict__ eb) {
    int b = blockIdx.x, cc = blockIdx.y;
    int tid = threadIdx.x;
    float r[NEXP];
#pragma unroll
    for (int e = 0; e < NEXP; e++) r[e] = rw[b * NEXP + e];

    for (int i = tid; i < 2304; i += 256) {
        int t    = i >> 8;
        int r2   = i & 255;
        int mt   = r2 >> 7;
        int lane = (r2 >> 2) & 31;
        int w    = r2 & 3;
        int g = lane >> 2, tig = lane & 3;
        int co = mt * 16 + g + (w & 1) * 8;
        int ci = cc * 16 + 2 * tig + (w >> 1) * 8;
        int src = co * (CIN_ * 9) + ci * 9 + t;
        float s_lo = 0.f, s_hi = 0.f;
#pragma unroll
        for (int e = 0; e < NEXP; e++) {
            s_lo += r[e] * ew[e * NPARAM + src];
            s_hi += r[e] * ew[e * NPARAM + src + 9];   // ci+1
        }
        g_wt_h[(b * 2 + cc) * 2304 + i] = pack_f16x2(s_hi, s_lo);
    }
    if (cc == 0 && tid < COUT_) {
        float s = 0.f;
#pragma unroll
        for (int e = 0; e < NEXP; e++) s += r[e] * eb[e * COUT_ + tid];
        g_bias[b * COUT_ + tid] = s;
    }
}

// ---------------------------------------------------------------------------
// stage 16 planes of one job into scr (plane p at p*PS + row*RAWP + col).
// ---------------------------------------------------------------------------
__device__ __forceinline__ void stage_raw(uint32_t scr, const float* __restrict__ xq,
                                          int h0, int w0, int tid) {
    for (int i = tid; i < 2560; i += 256) {            // interior 16B
        int v    = i & 15;
        int rest = i >> 4;
        int pl   = rest / 10;
        int row  = rest - pl * 10;
        int ih   = h0 - 1 + row;
        bool ok = (unsigned)ih < 256u;
        const float* src = xq + (size_t)pl * (HW_ * HW_) + (ok ? ih * HW_ : 0) + w0 + 4 * v;
        cp_async16z(scr + (uint32_t)(pl * PS + row * RAWP + 4 + 4 * v) * 4,
                    src, ok ? 16u : 0u);
    }
    for (int i = tid; i < 320; i += 256) {             // halo scalars
        int side = i & 1;
        int rest = i >> 1;
        int pl   = rest / 10;
        int row  = rest - pl * 10;
        int ih = h0 - 1 + row;
        int iw = side ? (w0 + 64) : (w0 - 1);
        bool ok = ((unsigned)ih < 256u) && ((unsigned)iw < 256u);
        const float* src = xq + (size_t)pl * (HW_ * HW_) + (ok ? (ih * HW_ + iw) : 0);
        cp_async4(scr + (uint32_t)(pl * PS + row * RAWP + (side ? 68 : 3)) * 4,
                  src, ok ? 4u : 0u);
    }
}

// ---------------------------------------------------------------------------
// compute one 16-ci half directly from raw f32 scr, packing B frags on the fly.
// lane reads planes 2tig,2tig+1 (B0) and 2(tig+4),2(tig+4)+1 (B1).
// ---------------------------------------------------------------------------
__device__ __forceinline__ void compute_direct(const float* sc, const uint32_t* ws,
                                               float acc[2][2][4][4],
                                               int lane, int g, int tig, int wy, int wh) {
    const uint4* wf = (const uint4*)ws + lane;
    const float* p0 = sc + (2 * tig) * PS + (2 * wy) * RAWP + wh * 32 + g + 3;

#pragma unroll
    for (int kw = 0; kw < 3; kw++) {
        uint32_t B0[4][4], B1[4][4];
#pragma unroll
        for (int xr = 0; xr < 4; xr++) {
#pragma unroll
            for (int nt = 0; nt < 4; nt++) {
                const int off = xr * RAWP + kw + nt * 8;
                B0[xr][nt] = pack_f16x2(p0[off + PS],     p0[off]);
                B1[xr][nt] = pack_f16x2(p0[off + 9 * PS], p0[off + 8 * PS]);
            }
        }
#pragma unroll
        for (int kh = 0; kh < 3; kh++) {
            const int t = kh * 3 + kw;
            uint4 q0 = wf[(t * 2) * 32];
            uint4 q1 = wf[(t * 2 + 1) * 32];
            uint32_t a0[4] = {q0.x, q0.y, q0.z, q0.w};
            uint32_t a1[4] = {q1.x, q1.y, q1.z, q1.w};
#pragma unroll
            for (int r = 0; r < 2; r++) {
                const int xr = r + kh;
#pragma unroll
                for (int nt = 0; nt < 4; nt++) {
                    mma_f16(acc[r][0][nt], a0, B0[xr][nt], B1[xr][nt]);
                    mma_f16(acc[r][1][nt], a1, B0[xr][nt], B1[xr][nt]);
                }
            }
        }
    }
}

__device__ __forceinline__ void store_tile(float acc[2][2][4][4], float* __restrict__ out,
                                           const float* bs, int b, int oh0, int w0,
                                           int g, int tig, int wy, int wh) {
#pragma unroll
    for (int r = 0; r < 2; r++) {
        const int oh = oh0 + 2 * wy + r;
#pragma unroll
        for (int mt = 0; mt < 2; mt++) {
#pragma unroll
            for (int nt = 0; nt < 4; nt++) {
                int co = mt * 16 + g;
                int pw = w0 + wh * 32 + nt * 8 + 2 * tig;
                float2 v0, v1;
                v0.x = acc[r][mt][nt][0] + bs[co];
                v0.y = acc[r][mt][nt][1] + bs[co];
                v1.x = acc[r][mt][nt][2] + bs[co + 8];
                v1.y = acc[r][mt][nt][3] + bs[co + 8];
                *(float2*)&out[(((size_t)b * COUT_ + co)     * HW_ + oh) * HW_ + pw] = v0;
                *(float2*)&out[(((size_t)b * COUT_ + co + 8) * HW_ + oh) * HW_ + pw] = v1;
            }
        }
    }
}

// ---------------------------------------------------------------------------
// Kernel 2: conv. Grid (4, 16, 16); 256 threads, 8 warps; 2 h-tiles per CTA.
// jobs jj=0..3: tile = jj>>1 (h0 = hb + 8*tile), half = jj&1.
// Per job: wait0 -> bar -> stage(jj+1) commit -> compute_direct(jj).
// ---------------------------------------------------------------------------
__global__ __launch_bounds__(256, 2)
void condconv_mma_kernel(const float* __restrict__ x, float* __restrict__ out) {
    extern __shared__ float sm[];
    const uint32_t sbase = smem_u32(sm);

    const int b  = blockIdx.z;
    const int hb = blockIdx.y * 16;      // 2-tile strip base row
    const int w0 = blockIdx.x * 64;
    const int tid = threadIdx.x;
    const int lane = tid & 31, wid = tid >> 5;
    const int g = lane >> 2, tig = lane & 3;
    const int wy = wid >> 1, wh = wid & 1;

    const uint32_t* gw = g_wt_h + b * 4608;
    const float* xb = x + (size_t)b * CIN_ * HW_ * HW_;
    const uint32_t scr_a[2] = {sbase + SCR0_U * 4, sbase + SCR1_U * 4};
    const float*   scr_p[2] = {sm + SCR0_U, sm + SCR1_U};
    const uint32_t* ws = (const uint32_t*)(sm + WS_U);

    if (tid < COUT_) sm[BIAS_U + tid] = g_bias[b * COUT_ + tid];

    // prologue: weights (both halves) + raw job0 in one cp.async group
    for (int i = tid; i < 1152; i += 256)
        cp_async16(sbase + (WS_U + i * 4) * 4, gw + i * 4);
    stage_raw(scr_a[0], xb, hb, w0, tid);
    CP_COMMIT();

    float acc[2][2][4][4];
#pragma unroll
    for (int r = 0; r < 2; r++)
#pragma unroll
        for (int mt = 0; mt < 2; mt++)
#pragma unroll
            for (int nt = 0; nt < 4; nt++)
#pragma unroll
                for (int i = 0; i < 4; i++) acc[r][mt][nt][i] = 0.f;

#pragma unroll 1
    for (int jj = 0; jj < 4; jj++) {
        CP_WAIT0();
        __syncthreads();                 // raw(jj) visible; scr[(jj+1)&1] free

        if (jj < 3) {                    // prefetch raw(jj+1) under compute(jj)
            int nj = jj + 1;
            stage_raw(scr_a[nj & 1], xb + (size_t)((nj & 1) * 16) * (HW_ * HW_),
                      hb + (nj >> 1) * 8, w0, tid);
            CP_COMMIT();
        }

        compute_direct(scr_p[jj & 1], ws + (jj & 1) * 2304, acc, lane, g, tig, wy, wh);

        if (jj == 1) {                   // tile 0 complete
            store_tile(acc, out, sm + BIAS_U, b, hb, w0, g, tig, wy, wh);
#pragma unroll
            for (int r = 0; r < 2; r++)
#pragma unroll
                for (int mt = 0; mt < 2; mt++)
#pragma unroll
                    for (int nt = 0; nt < 4; nt++)
#pragma unroll
                        for (int i = 0; i < 4; i++) acc[r][mt][nt][i] = 0.f;
        }
    }

    store_tile(acc, out, sm + BIAS_U, b, hb + 8, w0, g, tig, wy, wh);
}

// ---------------------------------------------------------------------------
extern "C" void kernel_launch(void* const* d_in, const int* in_sizes, int n_in,
                              void* d_out, int out_size) {
    const float* x  = (const float*)d_in[0];
    const float* rw = (const float*)d_in[1];
    const float* ew = (const float*)d_in[2];
    const float* eb = (const float*)d_in[3];
    float* out = (float*)d_out;

    condconv_prep_kernel<<<dim3(B_, 2), 256>>>(rw, ew, eb);

    cudaFuncSetAttribute(condconv_mma_kernel,
                         cudaFuncAttributeMaxDynamicSharedMemorySize, SMEM_BYTES);
    dim3 grid(HW_ / 64, HW_ / 16, B_);
    condconv_mma_kernel<<<grid, 256, SMEM_BYTES>>>(x, out);
}

// round 16
// speedup vs baseline: 1.3274x; 1.1529x over previous
#include <cuda_runtime.h>
#include <cstdint>

// CondConv2d via fp16 mma.sync.m16n8k16 implicit GEMM (f32 accumulate).
// R16: R11 (best: 88.1us conv) verbatim, plus (1) deliberate phase desync of
// co-resident CTAs via __nanosleep on odd bids, (2) widened prep grid.
// CTA = 8h x 64w x 32co, 2 h-tiles (4 jobs of 16 ci); 256 threads / 8 warps;
// warp = 2h x 32px x 32co.

#define B_    16
#define CIN_  32
#define HW_   256
#define COUT_ 32
#define NEXP  8
#define NPARAM 9216

// ---- smem layout in 4-byte units ----
#define RAWP   72                 // raw f32 pitch; raw col rc <-> iw = w0 - 4 + rc
#define SCR_U  0                  // 16 planes x 10 rows x 72 = 11520 words
#define XPH    76                 // 760 % 32 == 24 -> B-frag banks distinct
#define XSH_U  11520              // 8 jpairs x 10 rows x 76 = 6080 words
#define WS_U   17600              // 2 halves x 2304 words (k16 fragment order)
#define BIAS_U 22208
#define SMEM_U 22240
#define SMEM_BYTES (SMEM_U * 4)   // 88960 B -> 2 CTA/SM

__device__ uint32_t g_wt_h[B_ * 4608];   // [b][cc][t][mt][lane][w] f16x2 words
__device__ float    g_bias[B_ * COUT_];

__device__ __forceinline__ uint32_t smem_u32(const void* p) {
    uint32_t a;
    asm("{ .reg .u64 t; cvta.to.shared.u64 t, %1; cvt.u32.u64 %0, t; }" : "=r"(a) : "l"(p));
    return a;
}
__device__ __forceinline__ uint32_t pack_f16x2(float hi, float lo) {
    uint32_t d;
    asm("cvt.rn.f16x2.f32 %0, %1, %2;" : "=r"(d) : "f"(hi), "f"(lo));
    return d;
}
__device__ __forceinline__ void mma_f16(float c[4], const uint32_t a[4],
                                        uint32_t b0, uint32_t b1) {
    asm volatile(
        "mma.sync.aligned.m16n8k16.row.col.f32.f16.f16.f32 "
        "{%0,%1,%2,%3}, {%4,%5,%6,%7}, {%8,%9}, {%0,%1,%2,%3};"
        : "+f"(c[0]), "+f"(c[1]), "+f"(c[2]), "+f"(c[3])
        : "r"(a[0]), "r"(a[1]), "r"(a[2]), "r"(a[3]), "r"(b0), "r"(b1));
}
__device__ __forceinline__ void cp_async4(uint32_t dst, const void* src, uint32_t sz) {
    asm volatile("cp.async.ca.shared.global [%0], [%1], 4, %2;"
                 :: "r"(dst), "l"(src), "r"(sz) : "memory");
}
__device__ __forceinline__ void cp_async16(uint32_t dst, const void* src) {
    asm volatile("cp.async.cg.shared.global [%0], [%1], 16;"
                 :: "r"(dst), "l"(src) : "memory");
}
__device__ __forceinline__ void cp_async16z(uint32_t dst, const void* src, uint32_t sz) {
    asm volatile("cp.async.cg.shared.global [%0], [%1], 16, %2;"
                 :: "r"(dst), "l"(src), "r"(sz) : "memory");
}
#define CP_COMMIT() asm volatile("cp.async.commit_group;" ::: "memory")
#define CP_WAIT0()  asm volatile("cp.async.wait_group 0;" ::: "memory")

// ---------------------------------------------------------------------------
// Kernel 1: mix experts -> fragment-ordered fp16 weights + bias.
// Grid (16, 8): block (b, qq) computes words [qq*576, (qq+1)*576) of b's 4608.
// word index (per b): ((cc*9 + t)*2 + mt)*128 + lane*4 + w
//   co = mt*16 + g + (w&1)*8 ; ci = cc*16 + 2*tig + (w>>1)*8, pack {ci, ci+1}.
// ---------------------------------------------------------------------------
__global__ void condconv_prep_kernel(const float* __restrict__ rw,
                                     const float* __restrict__ ew,
                                     const float* __restrict__ eb) {
    int b = blockIdx.x, qq = blockIdx.y;
    int tid = threadIdx.x;
    float r[NEXP];
#pragma unroll
    for (int e = 0; e < NEXP; e++) r[e] = rw[b * NEXP + e];

    for (int k = tid; k < 576; k += 256) {
        int i  = qq * 576 + k;           // 0..4607
        int cc = i / 2304;
        int i2 = i - cc * 2304;
        int t    = i2 >> 8;
        int r2   = i2 & 255;
        int mt   = r2 >> 7;
        int lane = (r2 >> 2) & 31;
        int w    = r2 & 3;
        int g = lane >> 2, tig = lane & 3;
        int co = mt * 16 + g + (w & 1) * 8;
        int ci = cc * 16 + 2 * tig + (w >> 1) * 8;
        int src = co * (CIN_ * 9) + ci * 9 + t;
        float s_lo = 0.f, s_hi = 0.f;
#pragma unroll
        for (int e = 0; e < NEXP; e++) {
            s_lo += r[e] * ew[e * NPARAM + src];
            s_hi += r[e] * ew[e * NPARAM + src + 9];   // ci+1
        }
        g_wt_h[b * 4608 + i] = pack_f16x2(s_hi, s_lo);
    }
    if (qq == 0 && tid < COUT_) {
        float s = 0.f;
#pragma unroll
        for (int e = 0; e < NEXP; e++) s += r[e] * eb[e * COUT_ + tid];
        g_bias[b * COUT_ + tid] = s;
    }
}

// ---------------------------------------------------------------------------
// stage 16 planes of one (tile, half) job into scr as raw f32 (R11 verbatim).
// ---------------------------------------------------------------------------
__device__ __forceinline__ void stage_raw(uint32_t scr, const float* __restrict__ xq,
                                          int h0, int w0, int tid) {
    for (int i = tid; i < 2560; i += 256) {            // interior 16B
        int v    = i & 15;
        int rest = i >> 4;
        int pl   = rest / 10;
        int row  = rest - pl * 10;
        int ih   = h0 - 1 + row;
        bool ok = (unsigned)ih < 256u;
        const float* src = xq + (size_t)pl * (HW_ * HW_) + (ok ? ih * HW_ : 0) + w0 + 4 * v;
        cp_async16z(scr + (uint32_t)(pl * (10 * RAWP) + row * RAWP + 4 + 4 * v) * 4,
                    src, ok ? 16u : 0u);
    }
    for (int i = tid; i < 320; i += 256) {             // halo scalars
        int side = i & 1;
        int rest = i >> 1;
        int pl   = rest / 10;
        int row  = rest - pl * 10;
        int ih = h0 - 1 + row;
        int iw = side ? (w0 + 64) : (w0 - 1);
        bool ok = ((unsigned)ih < 256u) && ((unsigned)iw < 256u);
        const float* src = xq + (size_t)pl * (HW_ * HW_) + (ok ? (ih * HW_ + iw) : 0);
        cp_async4(scr + (uint32_t)(pl * (10 * RAWP) + row * RAWP + (side ? 68 : 3)) * 4,
                  src, ok ? 4u : 0u);
    }
}

// convert scr f32 (16 planes) -> xsh packed f16x2 (R11 verbatim)
__device__ __forceinline__ void convert_half(const float* scr, uint32_t* xsh, int tid) {
    for (int i = tid; i < 2800; i += 256) {
        int j   = i / 350;
        int r1  = i - j * 350;
        int row = r1 / 35;
        int p2  = r1 - row * 35;
        const float* s0 = scr + (2 * j)     * (10 * RAWP) + row * RAWP + 2 * p2;
        const float* s1 = scr + (2 * j + 1) * (10 * RAWP) + row * RAWP + 2 * p2;
        float2 f0 = *(const float2*)s0;
        float2 f1 = *(const float2*)s1;
        uint2 o;
        o.x = pack_f16x2(f1.x, f0.x);
        o.y = pack_f16x2(f1.y, f0.y);
        *(uint2*)(xsh + j * (10 * XPH) + row * XPH + 2 * p2) = o;
    }
}

// compute one 16-ci half (R11 verbatim)
__device__ __forceinline__ void compute_half(const uint32_t* xsh, const uint32_t* ws,
                                             float acc[2][2][4][4],
                                             int lane, int g, int tig, int wy, int wh) {
    const uint4* wf = (const uint4*)ws + lane;
    const uint32_t* xf = xsh + (2 * wy) * XPH + wh * 32 + g + 3 + tig * (10 * XPH);

#pragma unroll
    for (int kw = 0; kw < 3; kw++) {
        uint32_t B0[4][4], B1[4][4];
#pragma unroll
        for (int xr = 0; xr < 4; xr++) {
            const uint32_t* xt = xf + xr * XPH + kw;
#pragma unroll
            for (int nt = 0; nt < 4; nt++) {
                B0[xr][nt] = xt[nt * 8];
                B1[xr][nt] = xt[nt * 8 + 4 * (10 * XPH)];
            }
        }
#pragma unroll
        for (int kh = 0; kh < 3; kh++) {
            const int t = kh * 3 + kw;
            uint4 q0 = wf[(t * 2) * 32];
            uint4 q1 = wf[(t * 2 + 1) * 32];
            uint32_t a0[4] = {q0.x, q0.y, q0.z, q0.w};
            uint32_t a1[4] = {q1.x, q1.y, q1.z, q1.w};
#pragma unroll
            for (int r = 0; r < 2; r++) {
                const int xr = r + kh;
#pragma unroll
                for (int nt = 0; nt < 4; nt++) {
                    mma_f16(acc[r][0][nt], a0, B0[xr][nt], B1[xr][nt]);
                    mma_f16(acc[r][1][nt], a1, B0[xr][nt], B1[xr][nt]);
                }
            }
        }
    }
}

__device__ __forceinline__ void store_tile(float acc[2][2][4][4], float* __restrict__ out,
                                           const float* bs, int b, int oh0, int w0,
                                           int g, int tig, int wy, int wh) {
#pragma unroll
    for (int r = 0; r < 2; r++) {
        const int oh = oh0 + 2 * wy + r;
#pragma unroll
        for (int mt = 0; mt < 2; mt++) {
#pragma unroll
            for (int nt = 0; nt < 4; nt++) {
                int co = mt * 16 + g;
                int pw = w0 + wh * 32 + nt * 8 + 2 * tig;
                float2 v0, v1;
                v0.x = acc[r][mt][nt][0] + bs[co];
                v0.y = acc[r][mt][nt][1] + bs[co];
                v1.x = acc[r][mt][nt][2] + bs[co + 8];
                v1.y = acc[r][mt][nt][3] + bs[co + 8];
                *(float2*)&out[(((size_t)b * COUT_ + co)     * HW_ + oh) * HW_ + pw] = v0;
                *(float2*)&out[(((size_t)b * COUT_ + co + 8) * HW_ + oh) * HW_ + pw] = v1;
            }
        }
    }
}

// ---------------------------------------------------------------------------
// Kernel 2: conv. Grid (4, 16, 16); 256 threads, 8 warps; 2 h-tiles per CTA.
// jobs j=0..3: tile = j>>1 (h0 = hb + 8*tile), half = j&1.
// Odd-bid CTAs sleep ~1.6us after the prologue cp.async issue to anti-align
// convert/compute phases of the two co-resident CTAs per SM.
// ---------------------------------------------------------------------------
__global__ __launch_bounds__(256, 2)
void condconv_mma_kernel(const float* __restrict__ x, float* __restrict__ out) {
    extern __shared__ float sm[];
    const uint32_t sbase = smem_u32(sm);

    const int b  = blockIdx.z;
    const int hb = blockIdx.y * 16;      // 2-tile strip base row
    const int w0 = blockIdx.x * 64;
    const int tid = threadIdx.x;
    const int lane = tid & 31, wid = tid >> 5;
    const int g = lane >> 2, tig = lane & 3;
    const int wy = wid >> 1, wh = wid & 1;

    const uint32_t* gw = g_wt_h + b * 4608;
    const float* xb = x + (size_t)b * CIN_ * HW_ * HW_;
    uint32_t* xsh = (uint32_t*)(sm + XSH_U);
    const uint32_t* ws = (const uint32_t*)(sm + WS_U);
    const uint32_t scr_a = sbase + SCR_U * 4;

    if (tid < COUT_) sm[BIAS_U + tid] = g_bias[b * COUT_ + tid];

    // prologue: weights (both halves) + raw job0 in one cp.async group
    for (int i = tid; i < 1152; i += 256)
        cp_async16(sbase + (WS_U + i * 4) * 4, gw + i * 4);
    stage_raw(scr_a, xb, hb, w0, tid);
    CP_COMMIT();

    // phase desync: odd linear bid sleeps ~1.6us (prefetch already in flight)
    const int bid = blockIdx.x + (blockIdx.y << 2) + (blockIdx.z << 6);
    if (bid & 1) __nanosleep(1600);

    float acc[2][2][4][4];
#pragma unroll
    for (int r = 0; r < 2; r++)
#pragma unroll
        for (int mt = 0; mt < 2; mt++)
#pragma unroll
            for (int nt = 0; nt < 4; nt++)
#pragma unroll
                for (int i = 0; i < 4; i++) acc[r][mt][nt][i] = 0.f;

#pragma unroll 1
    for (int j = 0; j < 4; j++) {
        CP_WAIT0();
        __syncthreads();                 // raw(j) visible; xsh free
        convert_half(sm + SCR_U, xsh, tid);
        __syncthreads();                 // xsh ready; scr free

        if (j < 3) {                     // prefetch raw(j+1) under compute(j)
            int nj = j + 1;
            stage_raw(scr_a, xb + (size_t)((nj & 1) * 16) * (HW_ * HW_),
                      hb + (nj >> 1) * 8, w0, tid);
            CP_COMMIT();
        }

        compute_half(xsh, ws + (j & 1) * 2304, acc, lane, g, tig, wy, wh);

        if (j == 1) {                    // tile 0 complete
            store_tile(acc, out, sm + BIAS_U, b, hb, w0, g, tig, wy, wh);
#pragma unroll
            for (int r = 0; r < 2; r++)
#pragma unroll
                for (int mt = 0; mt < 2; mt++)
#pragma unroll
                    for (int nt = 0; nt < 4; nt++)
#pragma unroll
                        for (int i = 0; i < 4; i++) acc[r][mt][nt][i] = 0.f;
        }
    }

    store_tile(acc, out, sm + BIAS_U, b, hb + 8, w0, g, tig, wy, wh);
}

// ---------------------------------------------------------------------------
extern "C" void kernel_launch(void* const* d_in, const int* in_sizes, int n_in,
                              void* d_out, int out_size) {
    const float* x  = (const float*)d_in[0];
    const float* rw = (const float*)d_in[1];
    const float* ew = (const float*)d_in[2];
    const float* eb = (const float*)d_in[3];
    float* out = (float*)d_out;

    condconv_prep_kernel<<<dim3(B_, 8), 256>>>(rw, ew, eb);

    cudaFuncSetAttribute(condconv_mma_kernel,
                         cudaFuncAttributeMaxDynamicSharedMemorySize, SMEM_BYTES);
    dim3 grid(HW_ / 64, HW_ / 16, B_);
    condconv_mma_kernel<<<grid, 256, SMEM_BYTES>>>(x, out);
}

// round 17
// speedup vs baseline: 1.3868x; 1.0447x over previous
#include <cuda_runtime.h>
#include <cstdint>

// CondConv2d via fp16 mma.sync.m16n8k16 implicit GEMM (f32 accumulate).
// R17: R16 base (best: 94.2us total), nanosleep removed (falsified),
// compute_half restructured with a rolling 2-row B window to cut live
// registers (~128 -> ~100) and give ptxas room to pipeline LDS under MMAs.
// CTA = 8h x 64w x 32co, 2 h-tiles (4 jobs of 16 ci); 256 threads / 8 warps;
// warp = 2h x 32px x 32co.

#define B_    16
#define CIN_  32
#define HW_   256
#define COUT_ 32
#define NEXP  8
#define NPARAM 9216

// ---- smem layout in 4-byte units ----
#define RAWP   72                 // raw f32 pitch; raw col rc <-> iw = w0 - 4 + rc
#define SCR_U  0                  // 16 planes x 10 rows x 72 = 11520 words
#define XPH    76                 // 760 % 32 == 24 -> B-frag banks distinct
#define XSH_U  11520              // 8 jpairs x 10 rows x 76 = 6080 words
#define WS_U   17600              // 2 halves x 2304 words (k16 fragment order)
#define BIAS_U 22208
#define SMEM_U 22240
#define SMEM_BYTES (SMEM_U * 4)   // 88960 B -> 2 CTA/SM

__device__ uint32_t g_wt_h[B_ * 4608];   // [b][cc][t][mt][lane][w] f16x2 words
__device__ float    g_bias[B_ * COUT_];

__device__ __forceinline__ uint32_t smem_u32(const void* p) {
    uint32_t a;
    asm("{ .reg .u64 t; cvta.to.shared.u64 t, %1; cvt.u32.u64 %0, t; }" : "=r"(a) : "l"(p));
    return a;
}
__device__ __forceinline__ uint32_t pack_f16x2(float hi, float lo) {
    uint32_t d;
    asm("cvt.rn.f16x2.f32 %0, %1, %2;" : "=r"(d) : "f"(hi), "f"(lo));
    return d;
}
__device__ __forceinline__ void mma_f16(float c[4], const uint32_t a[4],
                                        uint32_t b0, uint32_t b1) {
    asm volatile(
        "mma.sync.aligned.m16n8k16.row.col.f32.f16.f16.f32 "
        "{%0,%1,%2,%3}, {%4,%5,%6,%7}, {%8,%9}, {%0,%1,%2,%3};"
        : "+f"(c[0]), "+f"(c[1]), "+f"(c[2]), "+f"(c[3])
        : "r"(a[0]), "r"(a[1]), "r"(a[2]), "r"(a[3]), "r"(b0), "r"(b1));
}
__device__ __forceinline__ void cp_async4(uint32_t dst, const void* src, uint32_t sz) {
    asm volatile("cp.async.ca.shared.global [%0], [%1], 4, %2;"
                 :: "r"(dst), "l"(src), "r"(sz) : "memory");
}
__device__ __forceinline__ void cp_async16(uint32_t dst, const void* src) {
    asm volatile("cp.async.cg.shared.global [%0], [%1], 16;"
                 :: "r"(dst), "l"(src) : "memory");
}
__device__ __forceinline__ void cp_async16z(uint32_t dst, const void* src, uint32_t sz) {
    asm volatile("cp.async.cg.shared.global [%0], [%1], 16, %2;"
                 :: "r"(dst), "l"(src), "r"(sz) : "memory");
}
#define CP_COMMIT() asm volatile("cp.async.commit_group;" ::: "memory")
#define CP_WAIT0()  asm volatile("cp.async.wait_group 0;" ::: "memory")

// ---------------------------------------------------------------------------
// Kernel 1: mix experts -> fragment-ordered fp16 weights + bias.
// Grid (16, 8): block (b, qq) computes words [qq*576, (qq+1)*576) of b's 4608.
// ---------------------------------------------------------------------------
__global__ void condconv_prep_kernel(const float* __restrict__ rw,
                                     const float* __restrict__ ew,
                                     const float* __restrict__ eb) {
    int b = blockIdx.x, qq = blockIdx.y;
    int tid = threadIdx.x;
    float r[NEXP];
#pragma unroll
    for (int e = 0; e < NEXP; e++) r[e] = rw[b * NEXP + e];

    for (int k = tid; k < 576; k += 256) {
        int i  = qq * 576 + k;
        int cc = i / 2304;
        int i2 = i - cc * 2304;
        int t    = i2 >> 8;
        int r2   = i2 & 255;
        int mt   = r2 >> 7;
        int lane = (r2 >> 2) & 31;
        int w    = r2 & 3;
        int g = lane >> 2, tig = lane & 3;
        int co = mt * 16 + g + (w & 1) * 8;
        int ci = cc * 16 + 2 * tig + (w >> 1) * 8;
        int src = co * (CIN_ * 9) + ci * 9 + t;
        float s_lo = 0.f, s_hi = 0.f;
#pragma unroll
        for (int e = 0; e < NEXP; e++) {
            s_lo += r[e] * ew[e * NPARAM + src];
            s_hi += r[e] * ew[e * NPARAM + src + 9];   // ci+1
        }
        g_wt_h[b * 4608 + i] = pack_f16x2(s_hi, s_lo);
    }
    if (qq == 0 && tid < COUT_) {
        float s = 0.f;
#pragma unroll
        for (int e = 0; e < NEXP; e++) s += r[e] * eb[e * COUT_ + tid];
        g_bias[b * COUT_ + tid] = s;
    }
}

// ---------------------------------------------------------------------------
// stage 16 planes of one (tile, half) job into scr as raw f32.
// ---------------------------------------------------------------------------
__device__ __forceinline__ void stage_raw(uint32_t scr, const float* __restrict__ xq,
                                          int h0, int w0, int tid) {
    for (int i = tid; i < 2560; i += 256) {            // interior 16B
        int v    = i & 15;
        int rest = i >> 4;
        int pl   = rest / 10;
        int row  = rest - pl * 10;
        int ih   = h0 - 1 + row;
        bool ok = (unsigned)ih < 256u;
        const float* src = xq + (size_t)pl * (HW_ * HW_) + (ok ? ih * HW_ : 0) + w0 + 4 * v;
        cp_async16z(scr + (uint32_t)(pl * (10 * RAWP) + row * RAWP + 4 + 4 * v) * 4,
                    src, ok ? 16u : 0u);
    }
    for (int i = tid; i < 320; i += 256) {             // halo scalars
        int side = i & 1;
        int rest = i >> 1;
        int pl   = rest / 10;
        int row  = rest - pl * 10;
        int ih = h0 - 1 + row;
        int iw = side ? (w0 + 64) : (w0 - 1);
        bool ok = ((unsigned)ih < 256u) && ((unsigned)iw < 256u);
        const float* src = xq + (size_t)pl * (HW_ * HW_) + (ok ? (ih * HW_ + iw) : 0);
        cp_async4(scr + (uint32_t)(pl * (10 * RAWP) + row * RAWP + (side ? 68 : 3)) * 4,
                  src, ok ? 4u : 0u);
    }
}

// convert scr f32 (16 planes) -> xsh packed f16x2
__device__ __forceinline__ void convert_half(const float* scr, uint32_t* xsh, int tid) {
    for (int i = tid; i < 2800; i += 256) {
        int j   = i / 350;
        int r1  = i - j * 350;
        int row = r1 / 35;
        int p2  = r1 - row * 35;
        const float* s0 = scr + (2 * j)     * (10 * RAWP) + row * RAWP + 2 * p2;
        const float* s1 = scr + (2 * j + 1) * (10 * RAWP) + row * RAWP + 2 * p2;
        float2 f0 = *(const float2*)s0;
        float2 f1 = *(const float2*)s1;
        uint2 o;
        o.x = pack_f16x2(f1.x, f0.x);
        o.y = pack_f16x2(f1.y, f0.y);
        *(uint2*)(xsh + j * (10 * XPH) + row * XPH + 2 * p2) = o;
    }
}

// ---------------------------------------------------------------------------
// compute one 16-ci half: rolling 2-row B window (16 live B regs).
// acc[0] pairs with row kh, acc[1] with row kh+1 (same math as before).
// ---------------------------------------------------------------------------
__device__ __forceinline__ void compute_half(const uint32_t* xsh, const uint32_t* ws,
                                             float acc[2][2][4][4],
                                             int lane, int g, int tig, int wy, int wh) {
    const uint4* wf = (const uint4*)ws + lane;
    const uint32_t* xf = xsh + (2 * wy) * XPH + wh * 32 + g + 3 + tig * (10 * XPH);

#pragma unroll
    for (int kw = 0; kw < 3; kw++) {
        uint32_t Ca0[4], Ca1[4], Cb0[4], Cb1[4];   // rows kh, kh+1
        {
            const uint32_t* x0 = xf + kw;          // xr = 0
            const uint32_t* x1 = xf + XPH + kw;    // xr = 1
#pragma unroll
            for (int nt = 0; nt < 4; nt++) {
                Ca0[nt] = x0[nt * 8];
                Ca1[nt] = x0[nt * 8 + 4 * (10 * XPH)];
                Cb0[nt] = x1[nt * 8];
                Cb1[nt] = x1[nt * 8 + 4 * (10 * XPH)];
            }
        }
#pragma unroll
        for (int kh = 0; kh < 3; kh++) {
            const int t = kh * 3 + kw;
            uint4 q0 = wf[(t * 2) * 32];
            uint4 q1 = wf[(t * 2 + 1) * 32];
            uint32_t a0[4] = {q0.x, q0.y, q0.z, q0.w};
            uint32_t a1[4] = {q1.x, q1.y, q1.z, q1.w};
#pragma unroll
            for (int nt = 0; nt < 4; nt++) {
                mma_f16(acc[0][0][nt], a0, Ca0[nt], Ca1[nt]);
                mma_f16(acc[0][1][nt], a1, Ca0[nt], Ca1[nt]);
                mma_f16(acc[1][0][nt], a0, Cb0[nt], Cb1[nt]);
                mma_f16(acc[1][1][nt], a1, Cb0[nt], Cb1[nt]);
            }
            if (kh < 2) {                          // rotate + load row kh+2
                const uint32_t* xn = xf + (kh + 2) * XPH + kw;
#pragma unroll
                for (int nt = 0; nt < 4; nt++) {
                    Ca0[nt] = Cb0[nt];
                    Ca1[nt] = Cb1[nt];
                    Cb0[nt] = xn[nt * 8];
                    Cb1[nt] = xn[nt * 8 + 4 * (10 * XPH)];
                }
            }
        }
    }
}

__device__ __forceinline__ void store_tile(float acc[2][2][4][4], float* __restrict__ out,
                                           const float* bs, int b, int oh0, int w0,
                                           int g, int tig, int wy, int wh) {
#pragma unroll
    for (int r = 0; r < 2; r++) {
        const int oh = oh0 + 2 * wy + r;
#pragma unroll
        for (int mt = 0; mt < 2; mt++) {
#pragma unroll
            for (int nt = 0; nt < 4; nt++) {
                int co = mt * 16 + g;
                int pw = w0 + wh * 32 + nt * 8 + 2 * tig;
                float2 v0, v1;
                v0.x = acc[r][mt][nt][0] + bs[co];
                v0.y = acc[r][mt][nt][1] + bs[co];
                v1.x = acc[r][mt][nt][2] + bs[co + 8];
                v1.y = acc[r][mt][nt][3] + bs[co + 8];
                *(float2*)&out[(((size_t)b * COUT_ + co)     * HW_ + oh) * HW_ + pw] = v0;
                *(float2*)&out[(((size_t)b * COUT_ + co + 8) * HW_ + oh) * HW_ + pw] = v1;
            }
        }
    }
}

// ---------------------------------------------------------------------------
// Kernel 2: conv. Grid (4, 16, 16); 256 threads, 8 warps; 2 h-tiles per CTA.
// jobs j=0..3: tile = j>>1 (h0 = hb + 8*tile), half = j&1.
// ---------------------------------------------------------------------------
__global__ __launch_bounds__(256, 2)
void condconv_mma_kernel(const float* __restrict__ x, float* __restrict__ out) {
    extern __shared__ float sm[];
    const uint32_t sbase = smem_u32(sm);

    const int b  = blockIdx.z;
    const int hb = blockIdx.y * 16;
    const int w0 = blockIdx.x * 64;
    const int tid = threadIdx.x;
    const int lane = tid & 31, wid = tid >> 5;
    const int g = lane >> 2, tig = lane & 3;
    const int wy = wid >> 1, wh = wid & 1;

    const uint32_t* gw = g_wt_h + b * 4608;
    const float* xb = x + (size_t)b * CIN_ * HW_ * HW_;
    uint32_t* xsh = (uint32_t*)(sm + XSH_U);
    const uint32_t* ws = (const uint32_t*)(sm + WS_U);
    const uint32_t scr_a = sbase + SCR_U * 4;

    if (tid < COUT_) sm[BIAS_U + tid] = g_bias[b * COUT_ + tid];

    // prologue: weights (both halves) + raw job0 in one cp.async group
    for (int i = tid; i < 1152; i += 256)
        cp_async16(sbase + (WS_U + i * 4) * 4, gw + i * 4);
    stage_raw(scr_a, xb, hb, w0, tid);
    CP_COMMIT();

    float acc[2][2][4][4];
#pragma unroll
    for (int r = 0; r < 2; r++)
#pragma unroll
        for (int mt = 0; mt < 2; mt++)
#pragma unroll
            for (int nt = 0; nt < 4; nt++)
#pragma unroll
                for (int i = 0; i < 4; i++) acc[r][mt][nt][i] = 0.f;

#pragma unroll 1
    for (int j = 0; j < 4; j++) {
        CP_WAIT0();
        __syncthreads();                 // raw(j) visible; xsh free
        convert_half(sm + SCR_U, xsh, tid);
        __syncthreads();                 // xsh ready; scr free

        if (j < 3) {                     // prefetch raw(j+1) under compute(j)
            int nj = j + 1;
            stage_raw(scr_a, xb + (size_t)((nj & 1) * 16) * (HW_ * HW_),
                      hb + (nj >> 1) * 8, w0, tid);
            CP_COMMIT();
        }

        compute_half(xsh, ws + (j & 1) * 2304, acc, lane, g, tig, wy, wh);

        if (j == 1) {                    // tile 0 complete
            store_tile(acc, out, sm + BIAS_U, b, hb, w0, g, tig, wy, wh);
#pragma unroll
            for (int r = 0; r < 2; r++)
#pragma unroll
                for (int mt = 0; mt < 2; mt++)
#pragma unroll
                    for (int nt = 0; nt < 4; nt++)
#pragma unroll
                        for (int i = 0; i < 4; i++) acc[r][mt][nt][i] = 0.f;
        }
    }

    store_tile(acc, out, sm + BIAS_U, b, hb + 8, w0, g, tig, wy, wh);
}

// ---------------------------------------------------------------------------
extern "C" void kernel_launch(void* const* d_in, const int* in_sizes, int n_in,
                              void* d_out, int out_size) {
    const float* x  = (const float*)d_in[0];
    const float* rw = (const float*)d_in[1];
    const float* ew = (const float*)d_in[2];
    const float* eb = (const float*)d_in[3];
    float* out = (float*)d_out;

    condconv_prep_kernel<<<dim3(B_, 8), 256>>>(rw, ew, eb);

    cudaFuncSetAttribute(condconv_mma_kernel,
                         cudaFuncAttributeMaxDynamicSharedMemorySize, SMEM_BYTES);
    dim3 grid(HW_ / 64, HW_ / 16, B_);
    condconv_mma_kernel<<<grid, 256, SMEM_BYTES>>>(x, out);
}